// round 16
// baseline (speedup 1.0000x reference)
#include <cuda_runtime.h>
#include <math.h>

// ---------------------------------------------------------------------------
// BNAF forward: D=8, H=512, B=2048, 4 masked layers + tanh, with log-det flow.
//
// Identities used:
//  * diag-block exp(ld) == normalized weight w  =>  logsumexp(sld + ld) =
//      m + log( exp(sld-m) . w_diag )   (plain dot product, no per-pair exp)
//  * with E = exp(-2|y|), r = 1/(1+E):
//      tanh(y) = sign(y)*(1-E)*r ;  sld_out = m + 2ln2 - 2|y| + log(Q*r^2)
//
// Layout trick: h1 and h2 are stored TRANSPOSED [k][m] = [512][2048] so the
// mid-layer GEMM's cp.async A-tiles arrive k-major and the inner loop needs
// only ONE broadcast LDS.128 for the A fragment (2 LDS + 16 FFMA per k).
// h3 stays [m][k] (layer 3 epilogue keeps coalesced stores; layer 4 reads rows).
// ---------------------------------------------------------------------------

#define B_  2048
#define H_  512
#define D_  8
#define TWO_LN2 1.38629436111989062f
#define NSM 152          // persistent grid for layer_mid (1 CTA/SM)

// scratch (device globals; no allocation allowed)
__device__ float g_wT1[8 * 512];      // [in][out]
__device__ float g_wT2[512 * 512];    // [in][out]
__device__ float g_wT3[512 * 512];    // [in][out]
__device__ float g_w4n[8 * 512];      // [out][in] (natural)
__device__ float g_logw1d[512];
__device__ float g_h1[H_ * B_];       // TRANSPOSED [k][m]
__device__ float g_h2[H_ * B_];       // TRANSPOSED [k][m]
__device__ float g_h3[B_ * H_];       // normal [m][k]
__device__ float g_sldA[B_ * H_];     // [b][i*64+o]
__device__ float g_sldB[B_ * H_];

__device__ __forceinline__ void cpa16(unsigned dst, const float* src) {
    asm volatile("cp.async.cg.shared.global [%0], [%1], 16;\n"
                 :: "r"(dst), "l"(src));
}
#define CP_COMMIT()  asm volatile("cp.async.commit_group;\n" ::)
#define CP_WAIT2()   asm volatile("cp.async.wait_group 2;\n" ::)

// ---------------------------------------------------------------------------
// merged prep: all 4 layers in ONE launch.
// ---------------------------------------------------------------------------
__global__ void prep_all_kernel(const float* __restrict__ W1, const float* __restrict__ g1,
                                const float* __restrict__ W2, const float* __restrict__ g2,
                                const float* __restrict__ W3, const float* __restrict__ g3,
                                const float* __restrict__ W4, const float* __restrict__ g4) {
    int blk = blockIdx.x;
    const float *W, *logg; int IN, OUT, ibshift, ob, layer, row0;
    if (blk < 64)       { layer = 1; W = W1; logg = g1; IN = 8;   OUT = 512; ibshift = 0; ob = 64; row0 = blk * 8; }
    else if (blk < 128) { layer = 2; W = W2; logg = g2; IN = 512; OUT = 512; ibshift = 6; ob = 64; row0 = (blk - 64) * 8; }
    else if (blk < 192) { layer = 3; W = W3; logg = g3; IN = 512; OUT = 512; ibshift = 6; ob = 64; row0 = (blk - 128) * 8; }
    else                { layer = 4; W = W4; logg = g4; IN = 512; OUT = 8;   ibshift = 6; ob = 1;  row0 = 0; }

    int o = row0 + threadIdx.y;
    if (o >= OUT) return;
    int lane = threadIdx.x;
    int i = o / ob;

    float sq = 0.0f;
    for (int c = lane; c < IN; c += 32) {
        int jb = c >> ibshift;
        float wv = W[o * IN + c];
        float v  = (jb == i) ? expf(wv) : (jb < i ? wv : 0.0f);
        sq += v * v;
    }
    #pragma unroll
    for (int off = 16; off; off >>= 1)
        sq += __shfl_xor_sync(0xffffffffu, sq, off);

    float scale = expf(logg[o]) / sqrtf(sq);
    for (int c = lane; c < IN; c += 32) {
        int jb = c >> ibshift;
        float wv = W[o * IN + c];
        float v  = (jb == i) ? expf(wv) : (jb < i ? wv : 0.0f);
        float w  = v * scale;
        if (layer == 1) {
            g_wT1[c * 512 + o] = w;
            if (c == i) g_logw1d[o] = logf(w);
        } else if (layer == 2) {
            g_wT2[c * 512 + o] = w;
        } else if (layer == 3) {
            g_wT3[c * 512 + o] = w;
        } else {
            g_w4n[o * 512 + c] = w;
        }
    }
}

// ---------------------------------------------------------------------------
// layer 1: per block 8 batch rows; weight column cached in registers.
// Writes h1 TRANSPOSED: g_h1[og][b].
// ---------------------------------------------------------------------------
__global__ void gemm1_kernel(const float* __restrict__ x,
                             const float* __restrict__ bias) {
    __shared__ float xs[8][8];
    int og = threadIdx.x;
    int b0 = blockIdx.x * 8;

    float w[8];
    #pragma unroll
    for (int k = 0; k < 8; k++) w[k] = g_wT1[k * 512 + og];
    float lw = g_logw1d[og];
    float bz = bias[og];

    if (og < 64) xs[og >> 3][og & 7] = x[b0 * 8 + og];
    __syncthreads();

    #pragma unroll
    for (int r = 0; r < 8; r++) {
        float acc = bz;
        #pragma unroll
        for (int k = 0; k < 8; k++) acc += w[k] * xs[r][k];
        float ay = fabsf(acc);
        float E  = __expf(-2.0f * ay);
        float rc = __fdividef(1.0f, 1.0f + E);
        int b = b0 + r;
        g_h1[og * B_ + b]    = copysignf((1.0f - E) * rc, acc);   // transposed
        g_sldA[b * 512 + og] = lw + TWO_LN2 - 2.0f * ay + __logf(rc * rc);
    }
}

// ---------------------------------------------------------------------------
// fused middle layer (2,3): persistent worklist + 4-stage cp.async pipeline
// masked GEMM + tanh + sld logsumexp update.
// A is TRANSPOSED in gmem [k][m] -> cp.async tiles are k-major, inner loop is
// 2 LDS.128 + 16 FFMA per k (FFMA-pipe bound).
// BM=BN=64, BK=16, 256 threads, 4x4/thread. Item t: i=7-(t>>5), m-blk=t&31.
// Serpentine over NSM=152 -> per-CTA balance by construction.
// layer==2 writes Hout TRANSPOSED (feeds layer 3); layer==3 writes normal.
// Epilogue Ps/wdS alias the stage buffers.
// ---------------------------------------------------------------------------
__global__ __launch_bounds__(256) void layer_mid_kernel(int layer,
                                                        const float* __restrict__ bias) {
    const float* AT   = (layer == 2) ? g_h1  : g_h2;   // [k][m]
    const float* wT   = (layer == 2) ? g_wT2 : g_wT3;  // [k][n]
    const float* Sin  = (layer == 2) ? g_sldA : g_sldB;
    float*       Sout = (layer == 2) ? g_sldB : g_sldA;

    __shared__ __align__(16) float AsS[4][16][68];   // 17408 B, k-major
    __shared__ __align__(16) float BsS[4][16][68];   // 17408 B
    __shared__ float mrow[64];

    float (*Ps)[68]  = (float (*)[68])&AsS[0][0][0];  // 64x68 == 4*16*68
    float (*wdS)[68] = (float (*)[68])&BsS[0][0][0];  // 64x68 == 4*16*68

    int tid = threadIdx.x;
    int tx = tid & 15, ty = tid >> 4;        // 4x4 tile: n=tx*4, m=ty*4
    int akr = tid >> 4, amc = (tid & 15) * 4;  // A cp map: k-row akr, 4 m's
    int bk  = tid >> 4, bn  = (tid & 15) * 4;  // B cp map: k-row bk, 4 n's
    unsigned aDst = (unsigned)__cvta_generic_to_shared(&AsS[0][akr][amc]);
    unsigned bDst = (unsigned)__cvta_generic_to_shared(&BsS[0][bk][bn]);
    const unsigned STAGE = 16 * 68 * 4;      // 4352 B
    int G = gridDim.x;

    for (int r = 0;; r++) {
        int t = r * G + ((r & 1) ? (G - 1 - (int)blockIdx.x) : (int)blockIdx.x);
        if (t >= 256) break;

        int i  = 7 - (t >> 5);
        int n0 = i * 64;
        int m0 = (t & 31) * 64;
        int ntiles = (i + 1) * 4;            // BK=16 tiles (mask skip); >= 4

        const float* Aptr = AT + akr * B_ + m0 + amc;   // row k=akr, cols m
        const float* Bptr = wT + bk * 512 + n0 + bn;

        // prologue: fill stages 0..2
        #pragma unroll
        for (int s = 0; s < 3; s++) {
            cpa16(aDst + s * STAGE, Aptr + s * 16 * B_);
            cpa16(bDst + s * STAGE, Bptr + s * 16 * 512);
            CP_COMMIT();
        }

        float acc[4][4] = {};

        for (int kt = 0; kt < ntiles; kt++) {
            CP_WAIT2();
            __syncthreads();
            int pf = kt + 3;
            if (pf < ntiles) {
                int s = pf & 3;
                cpa16(aDst + s * STAGE, Aptr + pf * 16 * B_);
                cpa16(bDst + s * STAGE, Bptr + pf * 16 * 512);
            }
            CP_COMMIT();                     // empty group on tail keeps count
            int cur = kt & 3;
            #pragma unroll
            for (int k = 0; k < 16; k++) {
                float4 a = *(const float4*)&AsS[cur][k][ty * 4];
                float4 b = *(const float4*)&BsS[cur][k][tx * 4];
                acc[0][0] += a.x * b.x; acc[0][1] += a.x * b.y;
                acc[0][2] += a.x * b.z; acc[0][3] += a.x * b.w;
                acc[1][0] += a.y * b.x; acc[1][1] += a.y * b.y;
                acc[1][2] += a.y * b.z; acc[1][3] += a.y * b.w;
                acc[2][0] += a.z * b.x; acc[2][1] += a.z * b.y;
                acc[2][2] += a.z * b.z; acc[2][3] += a.z * b.w;
                acc[3][0] += a.w * b.x; acc[3][1] += a.w * b.y;
                acc[3][2] += a.w * b.z; acc[3][3] += a.w * b.w;
            }
        }
        __syncthreads();   // all compute done before aliased epilogue writes

        // diag weight block from L2 (float4): wdS[j][o] = wT[(n0+j)*512+n0+o]
        for (int idx = tid; idx < 1024; idx += 256) {
            int o4 = (idx & 15) * 4, j = idx >> 4;
            *(float4*)(&wdS[j][o4]) =
                *(const float4*)(wT + (n0 + j) * 512 + n0 + o4);
        }

        // sld tile load + row max (row = 4 contiguous lanes -> shfl reduce)
        int row = tid >> 2, q = tid & 3;
        const float4* sp = (const float4*)(Sin + (m0 + row) * 512 + n0 + q * 16);
        float4 v4[4];
        float mx = -1e30f;
        #pragma unroll
        for (int c = 0; c < 4; c++) {
            v4[c] = sp[c];
            mx = fmaxf(mx, fmaxf(fmaxf(v4[c].x, v4[c].y), fmaxf(v4[c].z, v4[c].w)));
        }
        mx = fmaxf(mx, __shfl_xor_sync(0xffffffffu, mx, 1));
        mx = fmaxf(mx, __shfl_xor_sync(0xffffffffu, mx, 2));
        if (q == 0) mrow[row] = mx;

        {   // exponentiate into Ps[j][m]
            #pragma unroll
            for (int c = 0; c < 4; c++) {
                int j = q * 16 + c * 4;
                Ps[j + 0][row] = __expf(v4[c].x - mx);
                Ps[j + 1][row] = __expf(v4[c].y - mx);
                Ps[j + 2][row] = __expf(v4[c].z - mx);
                Ps[j + 3][row] = __expf(v4[c].w - mx);
            }
        }
        __syncthreads();

        // mini-GEMM: Q[m][o] = sum_j P[m][j] * wd[o][j]
        float qacc[4][4] = {};
        #pragma unroll 8
        for (int j = 0; j < 64; j++) {
            float4 a  = *(const float4*)(&Ps[j][ty * 4]);
            float4 bq = *(const float4*)(&wdS[j][tx * 4]);
            qacc[0][0] += a.x * bq.x; qacc[0][1] += a.x * bq.y;
            qacc[0][2] += a.x * bq.z; qacc[0][3] += a.x * bq.w;
            qacc[1][0] += a.y * bq.x; qacc[1][1] += a.y * bq.y;
            qacc[1][2] += a.y * bq.z; qacc[1][3] += a.y * bq.w;
            qacc[2][0] += a.z * bq.x; qacc[2][1] += a.z * bq.y;
            qacc[2][2] += a.z * bq.z; qacc[2][3] += a.z * bq.w;
            qacc[3][0] += a.w * bq.x; qacc[3][1] += a.w * bq.y;
            qacc[3][2] += a.w * bq.z; qacc[3][3] += a.w * bq.w;
        }

        // epilogue: h = tanh(y), sld_out in one logf
        float4 bz4 = *(const float4*)(bias + n0 + tx * 4);
        float bzv[4] = {bz4.x, bz4.y, bz4.z, bz4.w};
        #pragma unroll
        for (int ii = 0; ii < 4; ii++) {
            int m = m0 + ty * 4 + ii;
            float mr = mrow[ty * 4 + ii];
            float4 s4;
            float* spv = (float*)&s4;
            float hv[4];
            #pragma unroll
            for (int jj = 0; jj < 4; jj++) {
                float y  = acc[ii][jj] + bzv[jj];
                float ay = fabsf(y);
                float E  = __expf(-2.0f * ay);
                float rc = __fdividef(1.0f, 1.0f + E);
                hv[jj]  = copysignf((1.0f - E) * rc, y);
                spv[jj] = mr + TWO_LN2 - 2.0f * ay + __logf(qacc[ii][jj] * rc * rc);
            }
            if (layer == 2) {
                // transposed store: h2T[n][m] (feeds layer 3's k-major loads)
                #pragma unroll
                for (int jj = 0; jj < 4; jj++)
                    g_h2[(n0 + tx * 4 + jj) * B_ + m] = hv[jj];
            } else {
                float4 h4 = make_float4(hv[0], hv[1], hv[2], hv[3]);
                *(float4*)(&g_h3[m * 512 + n0 + tx * 4]) = h4;
            }
            *(float4*)(&Sout[m * 512 + n0 + tx * 4]) = s4;
        }
        __syncthreads();   // guard smem reuse by next item's prologue
    }
}

// ---------------------------------------------------------------------------
// fused layer 4: block handles 8 batch rows; w4 cached in smem once.
// warp i handles data dim i: 512-dot + tanh -> out[0:16384]; sld finale ->
// out[16384:32768].
// ---------------------------------------------------------------------------
__global__ void layer_last_kernel(const float* __restrict__ bias,
                                  float* __restrict__ out) {
    __shared__ float wsm[8 * 512];
    int tid = threadIdx.x;
    for (int idx = tid; idx < 4096; idx += 256) wsm[idx] = g_w4n[idx];
    __syncthreads();

    int i = tid >> 5, lane = tid & 31;
    float bz = bias[i];
    float wd0 = wsm[i * 512 + i * 64 + lane];
    float wd1 = wsm[i * 512 + i * 64 + lane + 32];

    int b0 = blockIdx.x * 8;
    #pragma unroll
    for (int r = 0; r < 8; r++) {
        int b = b0 + r;
        const float* hp = g_h3 + b * 512;
        float acc = 0.0f;
        #pragma unroll 4
        for (int k = lane; k < 512; k += 32) acc += hp[k] * wsm[i * 512 + k];
        #pragma unroll
        for (int off = 16; off; off >>= 1)
            acc += __shfl_xor_sync(0xffffffffu, acc, off);

        float y  = acc + bz;
        float ay = fabsf(y);
        float E  = __expf(-2.0f * ay);
        float rc = __fdividef(1.0f, 1.0f + E);

        const float* sp = g_sldA + b * 512 + i * 64;
        float s0 = sp[lane], s1 = sp[lane + 32];
        float m = fmaxf(s0, s1);
        #pragma unroll
        for (int off = 16; off; off >>= 1)
            m = fmaxf(m, __shfl_xor_sync(0xffffffffu, m, off));
        float p0 = __expf(s0 - m), p1 = __expf(s1 - m);
        float a = p0 * wd0 + p1 * wd1;
        #pragma unroll
        for (int off = 16; off; off >>= 1)
            a += __shfl_xor_sync(0xffffffffu, a, off);

        if (lane == 0) {
            out[b * 8 + i]           = copysignf((1.0f - E) * rc, y);
            out[B_ * D_ + b * 8 + i] = m + TWO_LN2 - 2.0f * ay + __logf(a * rc * rc);
        }
    }
}

// ---------------------------------------------------------------------------
extern "C" void kernel_launch(void* const* d_in, const int* in_sizes, int n_in,
                              void* d_out, int out_size) {
    (void)in_sizes; (void)n_in; (void)out_size;
    const float* x  = (const float*)d_in[0];
    const float* W1 = (const float*)d_in[1];
    const float* g1 = (const float*)d_in[2];
    const float* b1 = (const float*)d_in[3];
    const float* W2 = (const float*)d_in[4];
    const float* g2 = (const float*)d_in[5];
    const float* b2 = (const float*)d_in[6];
    const float* W3 = (const float*)d_in[7];
    const float* g3 = (const float*)d_in[8];
    const float* b3 = (const float*)d_in[9];
    const float* W4 = (const float*)d_in[10];
    const float* g4 = (const float*)d_in[11];
    const float* b4 = (const float*)d_in[12];
    float* out = (float*)d_out;

    prep_all_kernel<<<193, dim3(32, 8)>>>(W1, g1, W2, g2, W3, g3, W4, g4);
    gemm1_kernel<<<256, 512>>>(x, b1);
    layer_mid_kernel<<<NSM, 256>>>(2, b2);
    layer_mid_kernel<<<NSM, 256>>>(3, b3);
    layer_last_kernel<<<256, 256>>>(b4, out);
}

// round 17
// speedup vs baseline: 1.0919x; 1.0919x over previous
#include <cuda_runtime.h>
#include <math.h>

// ---------------------------------------------------------------------------
// BNAF forward: D=8, H=512, B=2048, 4 masked layers + tanh, with log-det flow.
//
// Identities used:
//  * diag-block exp(ld) == normalized weight w  =>  logsumexp(sld + ld) =
//      m + log( exp(sld-m) . w_diag )   (plain dot product, no per-pair exp)
//  * with E = exp(-2|y|), r = 1/(1+E):
//      tanh(y) = sign(y)*(1-E)*r ;  sld_out = m + 2ln2 - 2|y| + log(Q*r^2)
//
// Layout: h1, h2 stored TRANSPOSED [k][m] so mid-layer cp.async A-tiles are
// k-major (inner loop = 2 LDS.128 + 16 FFMA per k). All transposed stores are
// register-staged into float4s (no sector amplification).
// Diagonal weight block is reused directly from the B stage buffers: the last
// 4 BK16 stages of the masked mainloop are exactly wT[n0..n0+63][ntile].
// ---------------------------------------------------------------------------

#define B_  2048
#define H_  512
#define D_  8
#define TWO_LN2 1.38629436111989062f
#define NSM 152          // persistent grid for layer_mid (1 CTA/SM)

// scratch (device globals; no allocation allowed)
__device__ float g_wT1[8 * 512];      // [in][out]
__device__ float g_wT2[512 * 512];    // [in][out]
__device__ float g_wT3[512 * 512];    // [in][out]
__device__ float g_w4n[8 * 512];      // [out][in] (natural)
__device__ float g_logw1d[512];
__device__ float g_h1[H_ * B_];       // TRANSPOSED [k][m]
__device__ float g_h2[H_ * B_];       // TRANSPOSED [k][m]
__device__ float g_h3[B_ * H_];       // normal [m][k]
__device__ float g_sldA[B_ * H_];     // [b][i*64+o]
__device__ float g_sldB[B_ * H_];

__device__ __forceinline__ void cpa16(unsigned dst, const float* src) {
    asm volatile("cp.async.cg.shared.global [%0], [%1], 16;\n"
                 :: "r"(dst), "l"(src));
}
#define CP_COMMIT()  asm volatile("cp.async.commit_group;\n" ::)
#define CP_WAIT2()   asm volatile("cp.async.wait_group 2;\n" ::)

// ---------------------------------------------------------------------------
// merged prep: all 4 layers in ONE launch.
// ---------------------------------------------------------------------------
__global__ void prep_all_kernel(const float* __restrict__ W1, const float* __restrict__ g1,
                                const float* __restrict__ W2, const float* __restrict__ g2,
                                const float* __restrict__ W3, const float* __restrict__ g3,
                                const float* __restrict__ W4, const float* __restrict__ g4) {
    int blk = blockIdx.x;
    const float *W, *logg; int IN, OUT, ibshift, ob, layer, row0;
    if (blk < 64)       { layer = 1; W = W1; logg = g1; IN = 8;   OUT = 512; ibshift = 0; ob = 64; row0 = blk * 8; }
    else if (blk < 128) { layer = 2; W = W2; logg = g2; IN = 512; OUT = 512; ibshift = 6; ob = 64; row0 = (blk - 64) * 8; }
    else if (blk < 192) { layer = 3; W = W3; logg = g3; IN = 512; OUT = 512; ibshift = 6; ob = 64; row0 = (blk - 128) * 8; }
    else                { layer = 4; W = W4; logg = g4; IN = 512; OUT = 8;   ibshift = 6; ob = 1;  row0 = 0; }

    int o = row0 + threadIdx.y;
    if (o >= OUT) return;
    int lane = threadIdx.x;
    int i = o / ob;

    float sq = 0.0f;
    for (int c = lane; c < IN; c += 32) {
        int jb = c >> ibshift;
        float wv = W[o * IN + c];
        float v  = (jb == i) ? expf(wv) : (jb < i ? wv : 0.0f);
        sq += v * v;
    }
    #pragma unroll
    for (int off = 16; off; off >>= 1)
        sq += __shfl_xor_sync(0xffffffffu, sq, off);

    float scale = expf(logg[o]) / sqrtf(sq);
    for (int c = lane; c < IN; c += 32) {
        int jb = c >> ibshift;
        float wv = W[o * IN + c];
        float v  = (jb == i) ? expf(wv) : (jb < i ? wv : 0.0f);
        float w  = v * scale;
        if (layer == 1) {
            g_wT1[c * 512 + o] = w;
            if (c == i) g_logw1d[o] = logf(w);
        } else if (layer == 2) {
            g_wT2[c * 512 + o] = w;
        } else if (layer == 3) {
            g_wT3[c * 512 + o] = w;
        } else {
            g_w4n[o * 512 + c] = w;
        }
    }
}

// ---------------------------------------------------------------------------
// layer 1: per block 8 batch rows; weight column cached in registers.
// Writes h1 TRANSPOSED; the 8 h-values per thread are CONTIGUOUS in g_h1
// (g_h1[og*B + b0..b0+7]) -> two float4 stores, no sector amplification.
// ---------------------------------------------------------------------------
__global__ void gemm1_kernel(const float* __restrict__ x,
                             const float* __restrict__ bias) {
    __shared__ float xs[8][8];
    int og = threadIdx.x;
    int b0 = blockIdx.x * 8;

    float w[8];
    #pragma unroll
    for (int k = 0; k < 8; k++) w[k] = g_wT1[k * 512 + og];
    float lw = g_logw1d[og];
    float bz = bias[og];

    if (og < 64) xs[og >> 3][og & 7] = x[b0 * 8 + og];
    __syncthreads();

    float hv[8];
    #pragma unroll
    for (int r = 0; r < 8; r++) {
        float acc = bz;
        #pragma unroll
        for (int k = 0; k < 8; k++) acc += w[k] * xs[r][k];
        float ay = fabsf(acc);
        float E  = __expf(-2.0f * ay);
        float rc = __fdividef(1.0f, 1.0f + E);
        hv[r] = copysignf((1.0f - E) * rc, acc);
        g_sldA[(b0 + r) * 512 + og] = lw + TWO_LN2 - 2.0f * ay + __logf(rc * rc);
    }
    *(float4*)(&g_h1[og * B_ + b0])     = make_float4(hv[0], hv[1], hv[2], hv[3]);
    *(float4*)(&g_h1[og * B_ + b0 + 4]) = make_float4(hv[4], hv[5], hv[6], hv[7]);
}

// ---------------------------------------------------------------------------
// fused middle layer (2,3): persistent worklist + 4-stage cp.async pipeline
// masked GEMM + tanh + sld logsumexp update.
// A TRANSPOSED [k][m] -> k-major cp.async tiles; inner loop 2 LDS.128+16 FFMA.
// BM=BN=64, BK=16, 256 threads, 4x4/thread. Item t: i=7-(t>>5), m-blk=t&31.
// Serpentine over NSM=152 -> per-CTA balance by construction.
// After the mainloop the 4 B stages hold wT[n0..n0+63][ntile] == the diagonal
// block (ntiles multiple of 4): mini-GEMM reads BsS in place, no reload.
// Ps aliases the (dead) A stages only.
// layer==2 stores Hout TRANSPOSED via per-n float4s; layer==3 row float4s.
// ---------------------------------------------------------------------------
__global__ __launch_bounds__(256) void layer_mid_kernel(int layer,
                                                        const float* __restrict__ bias) {
    const float* AT   = (layer == 2) ? g_h1  : g_h2;   // [k][m]
    const float* wT   = (layer == 2) ? g_wT2 : g_wT3;  // [k][n]
    const float* Sin  = (layer == 2) ? g_sldA : g_sldB;
    float*       Sout = (layer == 2) ? g_sldB : g_sldA;

    __shared__ __align__(16) float AsS[4][16][68];   // 17408 B, k-major
    __shared__ __align__(16) float BsS[4][16][68];   // 17408 B
    __shared__ float mrow[64];

    float (*Ps)[68] = (float (*)[68])&AsS[0][0][0];  // 64x68 == 4*16*68

    int tid = threadIdx.x;
    int tx = tid & 15, ty = tid >> 4;        // 4x4 tile: n=tx*4, m=ty*4
    int akr = tid >> 4, amc = (tid & 15) * 4;  // A cp map: k-row akr, 4 m's
    int bk  = tid >> 4, bn  = (tid & 15) * 4;  // B cp map: k-row bk, 4 n's
    unsigned aDst = (unsigned)__cvta_generic_to_shared(&AsS[0][akr][amc]);
    unsigned bDst = (unsigned)__cvta_generic_to_shared(&BsS[0][bk][bn]);
    const unsigned STAGE = 16 * 68 * 4;      // 4352 B
    int G = gridDim.x;

    for (int r = 0;; r++) {
        int t = r * G + ((r & 1) ? (G - 1 - (int)blockIdx.x) : (int)blockIdx.x);
        if (t >= 256) break;

        int i  = 7 - (t >> 5);
        int n0 = i * 64;
        int m0 = (t & 31) * 64;
        int ntiles = (i + 1) * 4;            // BK=16 tiles (mask skip); mult of 4

        const float* Aptr = AT + akr * B_ + m0 + amc;   // row k=akr, cols m
        const float* Bptr = wT + bk * 512 + n0 + bn;

        // prologue: fill stages 0..2
        #pragma unroll
        for (int s = 0; s < 3; s++) {
            cpa16(aDst + s * STAGE, Aptr + s * 16 * B_);
            cpa16(bDst + s * STAGE, Bptr + s * 16 * 512);
            CP_COMMIT();
        }

        float acc[4][4] = {};

        for (int kt = 0; kt < ntiles; kt++) {
            CP_WAIT2();
            __syncthreads();
            int pf = kt + 3;
            if (pf < ntiles) {
                int s = pf & 3;
                cpa16(aDst + s * STAGE, Aptr + pf * 16 * B_);
                cpa16(bDst + s * STAGE, Bptr + pf * 16 * 512);
            }
            CP_COMMIT();                     // empty group on tail keeps count
            int cur = kt & 3;
            #pragma unroll
            for (int k = 0; k < 16; k++) {
                float4 a = *(const float4*)&AsS[cur][k][ty * 4];
                float4 b = *(const float4*)&BsS[cur][k][tx * 4];
                acc[0][0] += a.x * b.x; acc[0][1] += a.x * b.y;
                acc[0][2] += a.x * b.z; acc[0][3] += a.x * b.w;
                acc[1][0] += a.y * b.x; acc[1][1] += a.y * b.y;
                acc[1][2] += a.y * b.z; acc[1][3] += a.y * b.w;
                acc[2][0] += a.z * b.x; acc[2][1] += a.z * b.y;
                acc[2][2] += a.z * b.z; acc[2][3] += a.z * b.w;
                acc[3][0] += a.w * b.x; acc[3][1] += a.w * b.y;
                acc[3][2] += a.w * b.z; acc[3][3] += a.w * b.w;
            }
        }
        __syncthreads();   // mainloop reads done; A stages now dead (Ps alias)
        // BsS[s][k][o] (s=0..3) now holds wT[(n0+16s+k)*512 + n0+o]: the
        // diagonal block wd[j][o] with j = 16s+k. Use in place.

        // sld tile load + row max (row = 4 contiguous lanes -> shfl reduce)
        int row = tid >> 2, q = tid & 3;
        const float4* sp = (const float4*)(Sin + (m0 + row) * 512 + n0 + q * 16);
        float4 v4[4];
        float mx = -1e30f;
        #pragma unroll
        for (int c = 0; c < 4; c++) {
            v4[c] = sp[c];
            mx = fmaxf(mx, fmaxf(fmaxf(v4[c].x, v4[c].y), fmaxf(v4[c].z, v4[c].w)));
        }
        mx = fmaxf(mx, __shfl_xor_sync(0xffffffffu, mx, 1));
        mx = fmaxf(mx, __shfl_xor_sync(0xffffffffu, mx, 2));
        if (q == 0) mrow[row] = mx;

        {   // exponentiate into Ps[j][m]
            #pragma unroll
            for (int c = 0; c < 4; c++) {
                int j = q * 16 + c * 4;
                Ps[j + 0][row] = __expf(v4[c].x - mx);
                Ps[j + 1][row] = __expf(v4[c].y - mx);
                Ps[j + 2][row] = __expf(v4[c].z - mx);
                Ps[j + 3][row] = __expf(v4[c].w - mx);
            }
        }
        __syncthreads();

        // mini-GEMM: Q[m][o] = sum_j P[m][j] * wd[o][j], wd read from BsS
        float qacc[4][4] = {};
        #pragma unroll 4
        for (int j = 0; j < 64; j++) {
            float4 a  = *(const float4*)(&Ps[j][ty * 4]);
            float4 bq = *(const float4*)(&BsS[j >> 4][j & 15][tx * 4]);
            qacc[0][0] += a.x * bq.x; qacc[0][1] += a.x * bq.y;
            qacc[0][2] += a.x * bq.z; qacc[0][3] += a.x * bq.w;
            qacc[1][0] += a.y * bq.x; qacc[1][1] += a.y * bq.y;
            qacc[1][2] += a.y * bq.z; qacc[1][3] += a.y * bq.w;
            qacc[2][0] += a.z * bq.x; qacc[2][1] += a.z * bq.y;
            qacc[2][2] += a.z * bq.z; qacc[2][3] += a.z * bq.w;
            qacc[3][0] += a.w * bq.x; qacc[3][1] += a.w * bq.y;
            qacc[3][2] += a.w * bq.z; qacc[3][3] += a.w * bq.w;
        }

        // epilogue: h = tanh(y), sld_out in one logf
        float4 bz4 = *(const float4*)(bias + n0 + tx * 4);
        float bzv[4] = {bz4.x, bz4.y, bz4.z, bz4.w};
        float hv[4][4];
        #pragma unroll
        for (int ii = 0; ii < 4; ii++) {
            int m = m0 + ty * 4 + ii;
            float mr = mrow[ty * 4 + ii];
            float4 s4;
            float* spv = (float*)&s4;
            #pragma unroll
            for (int jj = 0; jj < 4; jj++) {
                float y  = acc[ii][jj] + bzv[jj];
                float ay = fabsf(y);
                float E  = __expf(-2.0f * ay);
                float rc = __fdividef(1.0f, 1.0f + E);
                hv[ii][jj] = copysignf((1.0f - E) * rc, y);
                spv[jj] = mr + TWO_LN2 - 2.0f * ay + __logf(qacc[ii][jj] * rc * rc);
            }
            *(float4*)(&Sout[m * 512 + n0 + tx * 4]) = s4;
        }
        if (layer == 2) {
            // transposed store, float4 over m: g_h2[n][m0+ty*4 .. +3]
            #pragma unroll
            for (int jj = 0; jj < 4; jj++) {
                float4 hh = make_float4(hv[0][jj], hv[1][jj], hv[2][jj], hv[3][jj]);
                *(float4*)(&g_h2[(n0 + tx * 4 + jj) * B_ + m0 + ty * 4]) = hh;
            }
        } else {
            #pragma unroll
            for (int ii = 0; ii < 4; ii++) {
                int m = m0 + ty * 4 + ii;
                *(float4*)(&g_h3[m * 512 + n0 + tx * 4]) =
                    make_float4(hv[ii][0], hv[ii][1], hv[ii][2], hv[ii][3]);
            }
        }
        __syncthreads();   // guard smem reuse by next item's prologue
    }
}

// ---------------------------------------------------------------------------
// fused layer 4: block handles 8 batch rows; w4 cached in smem once.
// warp i handles data dim i: 512-dot + tanh -> out[0:16384]; sld finale ->
// out[16384:32768].
// ---------------------------------------------------------------------------
__global__ void layer_last_kernel(const float* __restrict__ bias,
                                  float* __restrict__ out) {
    __shared__ float wsm[8 * 512];
    int tid = threadIdx.x;
    for (int idx = tid; idx < 4096; idx += 256) wsm[idx] = g_w4n[idx];
    __syncthreads();

    int i = tid >> 5, lane = tid & 31;
    float bz = bias[i];
    float wd0 = wsm[i * 512 + i * 64 + lane];
    float wd1 = wsm[i * 512 + i * 64 + lane + 32];

    int b0 = blockIdx.x * 8;
    #pragma unroll
    for (int r = 0; r < 8; r++) {
        int b = b0 + r;
        const float* hp = g_h3 + b * 512;
        float acc = 0.0f;
        #pragma unroll 4
        for (int k = lane; k < 512; k += 32) acc += hp[k] * wsm[i * 512 + k];
        #pragma unroll
        for (int off = 16; off; off >>= 1)
            acc += __shfl_xor_sync(0xffffffffu, acc, off);

        float y  = acc + bz;
        float ay = fabsf(y);
        float E  = __expf(-2.0f * ay);
        float rc = __fdividef(1.0f, 1.0f + E);

        const float* sp = g_sldA + b * 512 + i * 64;
        float s0 = sp[lane], s1 = sp[lane + 32];
        float m = fmaxf(s0, s1);
        #pragma unroll
        for (int off = 16; off; off >>= 1)
            m = fmaxf(m, __shfl_xor_sync(0xffffffffu, m, off));
        float p0 = __expf(s0 - m), p1 = __expf(s1 - m);
        float a = p0 * wd0 + p1 * wd1;
        #pragma unroll
        for (int off = 16; off; off >>= 1)
            a += __shfl_xor_sync(0xffffffffu, a, off);

        if (lane == 0) {
            out[b * 8 + i]           = copysignf((1.0f - E) * rc, y);
            out[B_ * D_ + b * 8 + i] = m + TWO_LN2 - 2.0f * ay + __logf(a * rc * rc);
        }
    }
}

// ---------------------------------------------------------------------------
extern "C" void kernel_launch(void* const* d_in, const int* in_sizes, int n_in,
                              void* d_out, int out_size) {
    (void)in_sizes; (void)n_in; (void)out_size;
    const float* x  = (const float*)d_in[0];
    const float* W1 = (const float*)d_in[1];
    const float* g1 = (const float*)d_in[2];
    const float* b1 = (const float*)d_in[3];
    const float* W2 = (const float*)d_in[4];
    const float* g2 = (const float*)d_in[5];
    const float* b2 = (const float*)d_in[6];
    const float* W3 = (const float*)d_in[7];
    const float* g3 = (const float*)d_in[8];
    const float* b3 = (const float*)d_in[9];
    const float* W4 = (const float*)d_in[10];
    const float* g4 = (const float*)d_in[11];
    const float* b4 = (const float*)d_in[12];
    float* out = (float*)d_out;

    prep_all_kernel<<<193, dim3(32, 8)>>>(W1, g1, W2, g2, W3, g3, W4, g4);
    gemm1_kernel<<<256, 512>>>(x, b1);
    layer_mid_kernel<<<NSM, 256>>>(2, b2);
    layer_mid_kernel<<<NSM, 256>>>(3, b3);
    layer_last_kernel<<<256, 256>>>(b4, out);
}